// round 15
// baseline (speedup 1.0000x reference)
#include <cuda_runtime.h>
#include <math.h>

#define TSTEPS 12
#define BATCH  1024
#define HID    256
#define NN     4096
#define DD     256
#define MALL   (TSTEPS*BATCH)   // 12288

// ---------------- scratch (static device globals; no allocation) ----------------
__device__ float g_coef[9*NN];
__device__ float g_Wp[DD*NN];
__device__ float g_t2[MALL*DD];
__device__ float g_t4[MALL*DD];
__device__ float g_xW[(size_t)MALL*3*HID];
__device__ float g_hs[MALL*HID];
__device__ float g_hA[BATCH*HID];
__device__ float g_hB[BATCH*HID];

__device__ __forceinline__ float sigm(float x) { return 1.0f / (1.0f + expf(-x)); }

__device__ __forceinline__ void cpa16(void* smem_dst, const void* gmem_src) {
    unsigned s = (unsigned)__cvta_generic_to_shared(smem_dst);
    asm volatile("cp.async.cg.shared.global [%0], [%1], 16;\n" :: "r"(s), "l"(gmem_src));
}
#define CP_COMMIT() asm volatile("cp.async.commit_group;\n" ::: "memory")
#define CP_WAIT0()  asm volatile("cp.async.wait_group 0;\n" ::: "memory")

__device__ __forceinline__ void mma_tf32(float* c, const unsigned* a, const unsigned* b) {
    asm volatile(
        "mma.sync.aligned.m16n8k8.row.col.f32.tf32.tf32.f32 "
        "{%0,%1,%2,%3}, {%4,%5,%6,%7}, {%8,%9}, {%0,%1,%2,%3};"
        : "+f"(c[0]), "+f"(c[1]), "+f"(c[2]), "+f"(c[3])
        : "r"(a[0]), "r"(a[1]), "r"(a[2]), "r"(a[3]), "r"(b[0]), "r"(b[1]));
}

// ---------------- stage 0: fold sparse A into W_gnn ----------------
__global__ void extract_coef(const float* __restrict__ A)
{
    int n = blockIdx.x * blockDim.x + threadIdx.x;
    if (n >= NN) return;
    const int offs[9] = {0,-1,1,64,-64,63,65,-65,-63};
#pragma unroll
    for (int j = 0; j < 9; j++) {
        int m = n + offs[j];
        g_coef[j*NN + n] = (m >= 0 && m < NN) ? A[(size_t)m * NN + n] : 0.0f;
    }
}

__global__ void build_wp(const float* __restrict__ Wg)
{
    int n = blockIdx.x * blockDim.x + threadIdx.x;
    int d = blockIdx.y;
    if (n >= NN) return;
    const int offs[9] = {0,-1,1,64,-64,63,65,-65,-63};
    float s = 0.0f;
#pragma unroll
    for (int j = 0; j < 9; j++) {
        int m = n + offs[j];
        if (m >= 0 && m < NN)
            s = fmaf(g_coef[j*NN + n], Wg[(size_t)d * NN + m], s);
    }
    g_Wp[(size_t)d * NN + n] = s;
}

// ---------------- tensor-core GEMM: C = act(A[M,K] @ W[N,K]^T + bias) ----------------
// tf32 m16n8k8, cp.async double-buffered. Block tile 128x128, BK=32, 8 warps 32x64.
// Smem rows stride 36 words -> fragment LDS bank = (4m+k)%32 = lane -> conflict-free.
template<int ACT>
__global__ __launch_bounds__(256, 2)
void mma_gemm(const float* __restrict__ A,
              const float* __restrict__ W,
              const float* __restrict__ bias,
              float* __restrict__ C,
              int M, int N, int K)
{
    extern __shared__ unsigned dsm[];
    unsigned* AsB = dsm;            // 2 stages * 128*36
    unsigned* WsB = dsm + 2*128*36; // 2 stages * 128*36

    const int tid  = threadIdx.x;
    const int wid  = tid >> 5;
    const int lane = tid & 31;
    const int gid  = lane >> 2;
    const int tig  = lane & 3;
    const int warp_m = wid & 3;
    const int warp_n = wid >> 2;
    const int mBase = blockIdx.y * 128;
    const int nBase = blockIdx.x * 128;

    float acc[2][8][4];
#pragma unroll
    for (int mi = 0; mi < 2; mi++)
#pragma unroll
        for (int ni = 0; ni < 8; ni++)
#pragma unroll
            for (int j = 0; j < 4; j++) acc[mi][ni][j] = 0.0f;

    auto stage = [&](int buf, int k0) {
#pragma unroll
        for (int i = 0; i < 4; i++) {
            int idx = tid + i * 256;
            int r = idx >> 3, c = (idx & 7) * 4;
            cpa16(&AsB[buf*128*36 + r*36 + c], A + (size_t)(mBase + r) * K + k0 + c);
        }
#pragma unroll
        for (int i = 0; i < 4; i++) {
            int idx = tid + i * 256;
            int r = idx >> 3, c = (idx & 7) * 4;
            cpa16(&WsB[buf*128*36 + r*36 + c], W + (size_t)(nBase + r) * K + k0 + c);
        }
        CP_COMMIT();
    };

    stage(0, 0);
    int buf = 0;
    for (int k0 = 0; k0 < K; k0 += 32) {
        CP_WAIT0();
        __syncthreads();
        if (k0 + 32 < K) stage(buf ^ 1, k0 + 32);

        const unsigned* As = AsB + buf*128*36;
        const unsigned* Ws = WsB + buf*128*36;
#pragma unroll
        for (int ks = 0; ks < 4; ks++) {
            const int kk = ks * 8;
            unsigned af[2][4], bf[8][2];
#pragma unroll
            for (int mi = 0; mi < 2; mi++) {
                int mr = warp_m * 32 + mi * 16 + gid;
                af[mi][0] = As[(mr    )*36 + kk + tig];
                af[mi][1] = As[(mr + 8)*36 + kk + tig];
                af[mi][2] = As[(mr    )*36 + kk + tig + 4];
                af[mi][3] = As[(mr + 8)*36 + kk + tig + 4];
            }
#pragma unroll
            for (int ni = 0; ni < 8; ni++) {
                int nc = warp_n * 64 + ni * 8 + gid;
                bf[ni][0] = Ws[nc*36 + kk + tig];
                bf[ni][1] = Ws[nc*36 + kk + tig + 4];
            }
#pragma unroll
            for (int mi = 0; mi < 2; mi++)
#pragma unroll
                for (int ni = 0; ni < 8; ni++)
                    mma_tf32(acc[mi][ni], af[mi], bf[ni]);
        }
        __syncthreads();
        buf ^= 1;
    }

#pragma unroll
    for (int mi = 0; mi < 2; mi++) {
        int m0 = mBase + warp_m * 32 + mi * 16 + gid;
#pragma unroll
        for (int ni = 0; ni < 8; ni++) {
            int n0 = nBase + warp_n * 64 + ni * 8 + tig * 2;
            float b0 = bias[n0], b1 = bias[n0 + 1];
            float v0 = acc[mi][ni][0] + b0;
            float v1 = acc[mi][ni][1] + b1;
            float v2 = acc[mi][ni][2] + b0;
            float v3 = acc[mi][ni][3] + b1;
            if (ACT) { v0 = sigm(v0); v1 = sigm(v1); v2 = sigm(v2); v3 = sigm(v3); }
            float2 lo; lo.x = v0; lo.y = v1;
            float2 hi; hi.x = v2; hi.y = v3;
            *reinterpret_cast<float2*>(C + (size_t)m0 * N + n0)       = lo;
            *reinterpret_cast<float2*>(C + (size_t)(m0 + 8) * N + n0) = hi;
        }
    }
}

// ---------------- fused GRU step: hW GEMM (all 3 gates of a j-slice) + gate math ----------------
// grid (4 j-slices, 16 batch tiles), 192 threads (6 warps: gate = wid/2, m-half = wid%2).
// C tile: 64 batch rows x 192 Whh rows ([gate*256 + jBase .. +64) per gate).
// h ping-pong: reads h_in (full rows), writes h_out (own j-slice) -> no cross-CTA race.
__global__ __launch_bounds__(192, 2)
void gru_step(const float* __restrict__ Whh, const float* __restrict__ bhh,
              const float* __restrict__ xW,
              const float* __restrict__ h_in, float* __restrict__ h_out,
              float* __restrict__ hs_out)
{
    extern __shared__ unsigned dsm[];
    unsigned* AsB = dsm;           // 2 stages * 64*36  = 4608 words
    unsigned* WsB = dsm + 4608;    // 2 stages * 192*36 = 13824 words
    float*    sC  = (float*)(dsm + 4608);   // reuse Ws region: 64 x 196 floats

    const int tid  = threadIdx.x;
    const int wid  = tid >> 5;
    const int lane = tid & 31;
    const int gid  = lane >> 2;
    const int tig  = lane & 3;
    const int gate = wid >> 1;
    const int mh   = wid & 1;
    const int bBase = blockIdx.y * 64;
    const int jBase = blockIdx.x * 64;

    float acc[2][8][4];
#pragma unroll
    for (int mi = 0; mi < 2; mi++)
#pragma unroll
        for (int ni = 0; ni < 8; ni++)
#pragma unroll
            for (int j = 0; j < 4; j++) acc[mi][ni][j] = 0.0f;

    auto stage = [&](int buf, int k0) {
#pragma unroll
        for (int i = 0; i < 3; i++) {          // 512 A quads / 192 threads
            int idx = tid + i * 192;
            if (idx < 512) {
                int r = idx >> 3, c = (idx & 7) * 4;
                cpa16(&AsB[buf*2304 + r*36 + c], h_in + (size_t)(bBase + r) * 256 + k0 + c);
            }
        }
#pragma unroll
        for (int i = 0; i < 8; i++) {          // 1536 W quads / 192 threads
            int idx = tid + i * 192;
            int r3 = idx >> 3, c = (idx & 7) * 4;
            int grow = (r3 >> 6) * 256 + jBase + (r3 & 63);
            cpa16(&WsB[buf*6912 + r3*36 + c], Whh + (size_t)grow * 256 + k0 + c);
        }
        CP_COMMIT();
    };

    stage(0, 0);
    int buf = 0;
    for (int k0 = 0; k0 < 256; k0 += 32) {
        CP_WAIT0();
        __syncthreads();
        if (k0 + 32 < 256) stage(buf ^ 1, k0 + 32);

        const unsigned* As = AsB + buf*2304;
        const unsigned* Ws = WsB + buf*6912;
#pragma unroll
        for (int ks = 0; ks < 4; ks++) {
            const int kk = ks * 8;
            unsigned af[2][4], bf[8][2];
#pragma unroll
            for (int mi = 0; mi < 2; mi++) {
                int mr = mh * 32 + mi * 16 + gid;
                af[mi][0] = As[(mr    )*36 + kk + tig];
                af[mi][1] = As[(mr + 8)*36 + kk + tig];
                af[mi][2] = As[(mr    )*36 + kk + tig + 4];
                af[mi][3] = As[(mr + 8)*36 + kk + tig + 4];
            }
#pragma unroll
            for (int ni = 0; ni < 8; ni++) {
                int nc = gate * 64 + ni * 8 + gid;
                bf[ni][0] = Ws[nc*36 + kk + tig];
                bf[ni][1] = Ws[nc*36 + kk + tig + 4];
            }
#pragma unroll
            for (int mi = 0; mi < 2; mi++)
#pragma unroll
                for (int ni = 0; ni < 8; ni++)
                    mma_tf32(acc[mi][ni], af[mi], bf[ni]);
        }
        __syncthreads();
        buf ^= 1;
    }

    // stage gate pre-activations (+bhh) into smem: sC[m][gate*64 + jn]
#pragma unroll
    for (int mi = 0; mi < 2; mi++) {
        int m0 = mh * 32 + mi * 16 + gid;
#pragma unroll
        for (int ni = 0; ni < 8; ni++) {
            int jn = ni * 8 + tig * 2;
            float b0 = bhh[gate * 256 + jBase + jn];
            float b1 = bhh[gate * 256 + jBase + jn + 1];
            int col = gate * 64 + jn;
            sC[(m0    )*196 + col    ] = acc[mi][ni][0] + b0;
            sC[(m0    )*196 + col + 1] = acc[mi][ni][1] + b1;
            sC[(m0 + 8)*196 + col    ] = acc[mi][ni][2] + b0;
            sC[(m0 + 8)*196 + col + 1] = acc[mi][ni][3] + b1;
        }
    }
    __syncthreads();

    // gate math + h update for this (btile, jslice)
    for (int i = tid; i < 64 * 64; i += 192) {
        int m = i >> 6, jn = i & 63;
        int b = bBase + m, j = jBase + jn;
        size_t xb = (size_t)b * 768 + j;
        float rv = sigm(xW[xb]        + sC[m*196 + jn]);
        float zv = sigm(xW[xb + 256]  + sC[m*196 + 64 + jn]);
        float nv = tanhf(xW[xb + 512] + rv * sC[m*196 + 128 + jn]);
        float hp = h_in[(size_t)b * 256 + j];
        float hn = (1.0f - zv) * nv + zv * hp;
        h_out[(size_t)b * 256 + j] = hn;
        if (hs_out) hs_out[(size_t)b * 256 + j] = hn;
    }
}

// ---------------- GRU init ----------------
__global__ void set_h(const float* __restrict__ src, float* __restrict__ dst)
{
    int i = blockIdx.x * blockDim.x + threadIdx.x;
    dst[i] = src[i];
}

// ---------------- final 3-layer sigmoid MLP ----------------
__global__ void final_mlp(const float* __restrict__ h,
                          const float* __restrict__ Wf0, const float* __restrict__ bf0,
                          const float* __restrict__ Wf1, const float* __restrict__ bf1,
                          const float* __restrict__ Wf2, const float* __restrict__ bf2,
                          float* __restrict__ out)
{
    __shared__ float sW0[16][257];
    __shared__ float sh [16][256];
    __shared__ float s1 [16][17];
    __shared__ float s2 [16][17];

    int tid = threadIdx.x;
    int bb  = blockIdx.x * 16;

    for (int i = tid; i < 16 * 256; i += 256) sW0[i / 256][i % 256] = Wf0[i];
    for (int i = tid; i < 16 * 256; i += 256) sh [i / 256][i % 256] = h[(size_t)bb * 256 + i];
    __syncthreads();

    int r = tid / 16, j = tid % 16;
    float a0 = bf0[j];
#pragma unroll 8
    for (int k = 0; k < 256; k++) a0 = fmaf(sh[r][k], sW0[j][k], a0);
    s1[r][j] = sigm(a0);
    __syncthreads();

    float a1 = bf1[j];
#pragma unroll
    for (int k = 0; k < 16; k++) a1 = fmaf(s1[r][k], Wf1[j * 16 + k], a1);
    s2[r][j] = sigm(a1);
    __syncthreads();

    if (j == 0) {
        float a2 = bf2[0];
#pragma unroll
        for (int k = 0; k < 16; k++) a2 = fmaf(s2[r][k], Wf2[k], a2);
        out[bb + r] = sigm(a2);
    }
}

// ---------------- launch ----------------
extern "C" void kernel_launch(void* const* d_in, const int* in_sizes, int n_in,
                              void* d_out, int out_size)
{
    const float* x     = (const float*)d_in[0];
    const float* h0    = (const float*)d_in[1];
    const float* Aadj  = (const float*)d_in[2];
    const float* W_gnn = (const float*)d_in[3];
    const float* b_gnn = (const float*)d_in[4];
    const float* W_lin = (const float*)d_in[5];
    const float* b_lin = (const float*)d_in[6];
    const float* Wih0  = (const float*)d_in[7];
    const float* Whh0  = (const float*)d_in[8];
    const float* bih0  = (const float*)d_in[9];
    const float* bhh0  = (const float*)d_in[10];
    const float* Wih1  = (const float*)d_in[11];
    const float* Whh1  = (const float*)d_in[12];
    const float* bih1  = (const float*)d_in[13];
    const float* bhh1  = (const float*)d_in[14];
    const float* Wf0   = (const float*)d_in[15];
    const float* bf0   = (const float*)d_in[16];
    const float* Wf1   = (const float*)d_in[17];
    const float* bf1   = (const float*)d_in[18];
    const float* Wf2   = (const float*)d_in[19];
    const float* bf2   = (const float*)d_in[20];
    float* out = (float*)d_out;

    float *p_Wp, *p_t2, *p_t4, *p_xW, *p_hs, *p_hA, *p_hB;
    cudaGetSymbolAddress((void**)&p_Wp, g_Wp);
    cudaGetSymbolAddress((void**)&p_t2, g_t2);
    cudaGetSymbolAddress((void**)&p_t4, g_t4);
    cudaGetSymbolAddress((void**)&p_xW, g_xW);
    cudaGetSymbolAddress((void**)&p_hs, g_hs);
    cudaGetSymbolAddress((void**)&p_hA, g_hA);
    cudaGetSymbolAddress((void**)&p_hB, g_hB);

    const int GEMM_SMEM = 2 * (2 * 128 * 36) * 4;            // 73728
    const int STEP_SMEM = (2*64*36 + 2*192*36) * 4;          // 73728
    cudaFuncSetAttribute(mma_gemm<1>, cudaFuncAttributeMaxDynamicSharedMemorySize, GEMM_SMEM);
    cudaFuncSetAttribute(mma_gemm<0>, cudaFuncAttributeMaxDynamicSharedMemorySize, GEMM_SMEM);
    cudaFuncSetAttribute(gru_step,    cudaFuncAttributeMaxDynamicSharedMemorySize, STEP_SMEM);

    // 0) fold A into W_gnn
    extract_coef<<<NN / 256, 256>>>(Aadj);
    build_wp<<<dim3(NN / 256, DD), 256>>>(W_gnn);

    // 1) t2 = sigmoid(x @ W'^T + b_gnn)   [12288,4096] x [4096,256]
    mma_gemm<1><<<dim3(DD / 128, MALL / 128), 256, GEMM_SMEM>>>(x, p_Wp, b_gnn, p_t2, MALL, DD, NN);

    // 2) t4 = sigmoid(t2 @ W_lin^T + b_lin)
    mma_gemm<1><<<dim3(DD / 128, MALL / 128), 256, GEMM_SMEM>>>(p_t2, W_lin, b_lin, p_t4, MALL, DD, DD);

    // 3) GRU layer 0
    mma_gemm<0><<<dim3(3 * HID / 128, MALL / 128), 256, GEMM_SMEM>>>(p_t4, Wih0, bih0, p_xW, MALL, 3 * HID, DD);
    set_h<<<BATCH * HID / 256, 256>>>(h0, p_hA);
    {
        float* hin = p_hA; float* hout = p_hB;
        for (int t = 0; t < TSTEPS; t++) {
            gru_step<<<dim3(4, 16), 192, STEP_SMEM>>>(Whh0, bhh0,
                p_xW + (size_t)t * BATCH * 3 * HID, hin, hout,
                p_hs + (size_t)t * BATCH * HID);
            float* tmp = hin; hin = hout; hout = tmp;
        }
    }

    // 4) GRU layer 1
    mma_gemm<0><<<dim3(3 * HID / 128, MALL / 128), 256, GEMM_SMEM>>>(p_hs, Wih1, bih1, p_xW, MALL, 3 * HID, HID);
    set_h<<<BATCH * HID / 256, 256>>>(h0 + BATCH * HID, p_hA);
    {
        float* hin = p_hA; float* hout = p_hB;
        for (int t = 0; t < TSTEPS; t++) {
            gru_step<<<dim3(4, 16), 192, STEP_SMEM>>>(Whh1, bhh1,
                p_xW + (size_t)t * BATCH * 3 * HID, hin, hout, nullptr);
            float* tmp = hin; hin = hout; hout = tmp;
        }
    }

    // 5) final MLP -> out [1024]  (after even #steps, final h is back in p_hA)
    final_mlp<<<BATCH / 16, 256>>>(p_hA, Wf0, bf0, Wf1, bf1, Wf2, bf2, out);
}

// round 16
// speedup vs baseline: 1.8109x; 1.8109x over previous
#include <cuda_runtime.h>
#include <math.h>

#define TSTEPS 12
#define BATCH  1024
#define HID    256
#define NN     4096
#define DD     256
#define MALL   (TSTEPS*BATCH)   // 12288

// ---------------- scratch (static device globals; no allocation) ----------------
__device__ float g_coef[9*NN];
__device__ float g_Wp[DD*NN];
__device__ float g_t2[MALL*DD];
__device__ float g_t4[MALL*DD];
__device__ float g_xW[(size_t)MALL*3*HID];
__device__ float g_hW[BATCH*3*HID];
__device__ float g_hs[MALL*HID];
__device__ float g_h [BATCH*HID];

__device__ __forceinline__ float sigm(float x) { return 1.0f / (1.0f + expf(-x)); }

__device__ __forceinline__ void cpa16(void* smem_dst, const void* gmem_src) {
    unsigned s = (unsigned)__cvta_generic_to_shared(smem_dst);
    asm volatile("cp.async.cg.shared.global [%0], [%1], 16;\n" :: "r"(s), "l"(gmem_src));
}
#define CP_COMMIT() asm volatile("cp.async.commit_group;\n" ::: "memory")
#define CP_WAIT0()  asm volatile("cp.async.wait_group 0;\n" ::: "memory")
#define CP_WAIT1()  asm volatile("cp.async.wait_group 1;\n" ::: "memory")

__device__ __forceinline__ void mma_tf32(float* c, const unsigned* a, const unsigned* b) {
    asm volatile(
        "mma.sync.aligned.m16n8k8.row.col.f32.tf32.tf32.f32 "
        "{%0,%1,%2,%3}, {%4,%5,%6,%7}, {%8,%9}, {%0,%1,%2,%3};"
        : "+f"(c[0]), "+f"(c[1]), "+f"(c[2]), "+f"(c[3])
        : "r"(a[0]), "r"(a[1]), "r"(a[2]), "r"(a[3]), "r"(b[0]), "r"(b[1]));
}

// ---------------- stage 0: fold sparse A into W_gnn ----------------
__global__ void extract_coef(const float* __restrict__ A)
{
    int n = blockIdx.x * blockDim.x + threadIdx.x;
    if (n >= NN) return;
    const int offs[9] = {0,-1,1,64,-64,63,65,-65,-63};
#pragma unroll
    for (int j = 0; j < 9; j++) {
        int m = n + offs[j];
        g_coef[j*NN + n] = (m >= 0 && m < NN) ? A[(size_t)m * NN + n] : 0.0f;
    }
}

__global__ void build_wp(const float* __restrict__ Wg)
{
    int n = blockIdx.x * blockDim.x + threadIdx.x;
    int d = blockIdx.y;
    if (n >= NN) return;
    const int offs[9] = {0,-1,1,64,-64,63,65,-65,-63};
    float s = 0.0f;
#pragma unroll
    for (int j = 0; j < 9; j++) {
        int m = n + offs[j];
        if (m >= 0 && m < NN)
            s = fmaf(g_coef[j*NN + n], Wg[(size_t)d * NN + m], s);
    }
    g_Wp[(size_t)d * NN + n] = s;
}

// ---------------- tensor-core GEMM: C = act(A[M,K] @ W[N,K]^T + bias) ----------------
// tf32 m16n8k8, 3-stage cp.async pipeline (wait_group 1), ONE __syncthreads per K-iter.
// Block tile (NWM*32) x 128, BK=32. Warp tile 32x64. Smem rows stride 36 words ->
// fragment LDS bank = (4m+k)%32 = lane -> conflict-free.
template<int NWM, int ACT>
__global__ __launch_bounds__(NWM*64, 2)
void mma_gemm(const float* __restrict__ A,
              const float* __restrict__ W,
              const float* __restrict__ bias,
              float* __restrict__ C,
              int M, int N, int K)
{
    constexpr int THREADS = NWM * 64;
    constexpr int BM = NWM * 32;
    constexpr int WL = 16 / NWM;                 // W-staging quads per thread
    constexpr int STW = (BM + 128) * 36;         // words per stage

    extern __shared__ unsigned dsm[];

    const int tid  = threadIdx.x;
    const int wid  = tid >> 5;
    const int lane = tid & 31;
    const int gid  = lane >> 2;
    const int tig  = lane & 3;
    const int warp_m = wid % NWM;
    const int warp_n = wid / NWM;
    const int mBase = blockIdx.y * BM;
    const int nBase = blockIdx.x * 128;

    float acc[2][8][4];
#pragma unroll
    for (int mi = 0; mi < 2; mi++)
#pragma unroll
        for (int ni = 0; ni < 8; ni++)
#pragma unroll
            for (int j = 0; j < 4; j++) acc[mi][ni][j] = 0.0f;

    auto stage = [&](int s, int k0) {
        unsigned* As = dsm + s * STW;
        unsigned* Ws = As + BM * 36;
#pragma unroll
        for (int i = 0; i < 4; i++) {
            int idx = tid + i * THREADS;
            int r = idx >> 3, c = (idx & 7) * 4;
            cpa16(&As[r*36 + c], A + (size_t)(mBase + r) * K + k0 + c);
        }
#pragma unroll
        for (int i = 0; i < WL; i++) {
            int idx = tid + i * THREADS;
            int r = idx >> 3, c = (idx & 7) * 4;
            cpa16(&Ws[r*36 + c], W + (size_t)(nBase + r) * K + k0 + c);
        }
        CP_COMMIT();
    };

    const int nIter = K >> 5;
    stage(0, 0);
    if (nIter > 1) stage(1, 32);

    for (int it = 0; it < nIter; it++) {
        if (it + 1 < nIter) { CP_WAIT1(); } else { CP_WAIT0(); }
        __syncthreads();
        if (it + 2 < nIter) stage((it + 2) % 3, (it + 2) << 5);

        const unsigned* As = dsm + (it % 3) * STW;
        const unsigned* Ws = As + BM * 36;
#pragma unroll
        for (int ks = 0; ks < 4; ks++) {
            const int kk = ks * 8;
            unsigned af[2][4], bf[8][2];
#pragma unroll
            for (int mi = 0; mi < 2; mi++) {
                int mr = warp_m * 32 + mi * 16 + gid;
                af[mi][0] = As[(mr    )*36 + kk + tig];
                af[mi][1] = As[(mr + 8)*36 + kk + tig];
                af[mi][2] = As[(mr    )*36 + kk + tig + 4];
                af[mi][3] = As[(mr + 8)*36 + kk + tig + 4];
            }
#pragma unroll
            for (int ni = 0; ni < 8; ni++) {
                int nc = warp_n * 64 + ni * 8 + gid;
                bf[ni][0] = Ws[nc*36 + kk + tig];
                bf[ni][1] = Ws[nc*36 + kk + tig + 4];
            }
#pragma unroll
            for (int mi = 0; mi < 2; mi++)
#pragma unroll
                for (int ni = 0; ni < 8; ni++)
                    mma_tf32(acc[mi][ni], af[mi], bf[ni]);
        }
    }

#pragma unroll
    for (int mi = 0; mi < 2; mi++) {
        int m0 = mBase + warp_m * 32 + mi * 16 + gid;
#pragma unroll
        for (int ni = 0; ni < 8; ni++) {
            int n0 = nBase + warp_n * 64 + ni * 8 + tig * 2;
            float b0 = bias[n0], b1 = bias[n0 + 1];
            float v0 = acc[mi][ni][0] + b0;
            float v1 = acc[mi][ni][1] + b1;
            float v2 = acc[mi][ni][2] + b0;
            float v3 = acc[mi][ni][3] + b1;
            if (ACT) { v0 = sigm(v0); v1 = sigm(v1); v2 = sigm(v2); v3 = sigm(v3); }
            float2 lo; lo.x = v0; lo.y = v1;
            float2 hi; hi.x = v2; hi.y = v3;
            *reinterpret_cast<float2*>(C + (size_t)m0 * N + n0)       = lo;
            *reinterpret_cast<float2*>(C + (size_t)(m0 + 8) * N + n0) = hi;
        }
    }
}

// ---------------- GRU pieces (R14-proven structure) ----------------
__global__ void set_h(const float* __restrict__ src)
{
    int i = blockIdx.x * blockDim.x + threadIdx.x;
    g_h[i] = src[i];
}

__global__ void gru_gate(const float* __restrict__ xW,
                         const float* __restrict__ hW,
                         float* __restrict__ h,
                         float* __restrict__ hs_out)
{
    int idx = blockIdx.x * blockDim.x + threadIdx.x;
    int b = idx / HID, j = idx % HID;
    size_t base = (size_t)b * 3 * HID;
    float r = sigm(xW[base + j]          + hW[base + j]);
    float z = sigm(xW[base + HID + j]    + hW[base + HID + j]);
    float n = tanhf(xW[base + 2*HID + j] + r * hW[base + 2*HID + j]);
    float hp = h[idx];
    float hn = (1.0f - z) * n + z * hp;
    h[idx] = hn;
    if (hs_out) hs_out[idx] = hn;
}

// ---------------- final 3-layer sigmoid MLP ----------------
__global__ void final_mlp(const float* __restrict__ h,
                          const float* __restrict__ Wf0, const float* __restrict__ bf0,
                          const float* __restrict__ Wf1, const float* __restrict__ bf1,
                          const float* __restrict__ Wf2, const float* __restrict__ bf2,
                          float* __restrict__ out)
{
    __shared__ float sW0[16][257];
    __shared__ float sh [16][256];
    __shared__ float s1 [16][17];
    __shared__ float s2 [16][17];

    int tid = threadIdx.x;
    int bb  = blockIdx.x * 16;

    for (int i = tid; i < 16 * 256; i += 256) sW0[i / 256][i % 256] = Wf0[i];
    for (int i = tid; i < 16 * 256; i += 256) sh [i / 256][i % 256] = h[(size_t)bb * 256 + i];
    __syncthreads();

    int r = tid / 16, j = tid % 16;
    float a0 = bf0[j];
#pragma unroll 8
    for (int k = 0; k < 256; k++) a0 = fmaf(sh[r][k], sW0[j][k], a0);
    s1[r][j] = sigm(a0);
    __syncthreads();

    float a1 = bf1[j];
#pragma unroll
    for (int k = 0; k < 16; k++) a1 = fmaf(s1[r][k], Wf1[j * 16 + k], a1);
    s2[r][j] = sigm(a1);
    __syncthreads();

    if (j == 0) {
        float a2 = bf2[0];
#pragma unroll
        for (int k = 0; k < 16; k++) a2 = fmaf(s2[r][k], Wf2[k], a2);
        out[bb + r] = sigm(a2);
    }
}

// ---------------- launch ----------------
extern "C" void kernel_launch(void* const* d_in, const int* in_sizes, int n_in,
                              void* d_out, int out_size)
{
    const float* x     = (const float*)d_in[0];
    const float* h0    = (const float*)d_in[1];
    const float* Aadj  = (const float*)d_in[2];
    const float* W_gnn = (const float*)d_in[3];
    const float* b_gnn = (const float*)d_in[4];
    const float* W_lin = (const float*)d_in[5];
    const float* b_lin = (const float*)d_in[6];
    const float* Wih0  = (const float*)d_in[7];
    const float* Whh0  = (const float*)d_in[8];
    const float* bih0  = (const float*)d_in[9];
    const float* bhh0  = (const float*)d_in[10];
    const float* Wih1  = (const float*)d_in[11];
    const float* Whh1  = (const float*)d_in[12];
    const float* bih1  = (const float*)d_in[13];
    const float* bhh1  = (const float*)d_in[14];
    const float* Wf0   = (const float*)d_in[15];
    const float* bf0   = (const float*)d_in[16];
    const float* Wf1   = (const float*)d_in[17];
    const float* bf1   = (const float*)d_in[18];
    const float* Wf2   = (const float*)d_in[19];
    const float* bf2   = (const float*)d_in[20];
    float* out = (float*)d_out;

    float *p_Wp, *p_t2, *p_t4, *p_xW, *p_hW, *p_hs, *p_h;
    cudaGetSymbolAddress((void**)&p_Wp, g_Wp);
    cudaGetSymbolAddress((void**)&p_t2, g_t2);
    cudaGetSymbolAddress((void**)&p_t4, g_t4);
    cudaGetSymbolAddress((void**)&p_xW, g_xW);
    cudaGetSymbolAddress((void**)&p_hW, g_hW);
    cudaGetSymbolAddress((void**)&p_hs, g_hs);
    cudaGetSymbolAddress((void**)&p_h,  g_h);

    const int SMEM4 = 3 * (128 + 128) * 36 * 4;   // 110592 B (NWM=4)
    const int SMEM2 = 3 * ( 64 + 128) * 36 * 4;   //  82944 B (NWM=2)
    cudaFuncSetAttribute(mma_gemm<4,1>, cudaFuncAttributeMaxDynamicSharedMemorySize, SMEM4);
    cudaFuncSetAttribute(mma_gemm<4,0>, cudaFuncAttributeMaxDynamicSharedMemorySize, SMEM4);
    cudaFuncSetAttribute(mma_gemm<2,0>, cudaFuncAttributeMaxDynamicSharedMemorySize, SMEM2);

    // 0) fold A into W_gnn
    extract_coef<<<NN / 256, 256>>>(Aadj);
    build_wp<<<dim3(NN / 256, DD), 256>>>(W_gnn);

    // 1) t2 = sigmoid(x @ W'^T + b_gnn)   [12288,4096] x [4096,256]
    mma_gemm<4,1><<<dim3(DD / 128, MALL / 128), 256, SMEM4>>>(x, p_Wp, b_gnn, p_t2, MALL, DD, NN);

    // 2) t4 = sigmoid(t2 @ W_lin^T + b_lin)
    mma_gemm<4,1><<<dim3(DD / 128, MALL / 128), 256, SMEM4>>>(p_t2, W_lin, b_lin, p_t4, MALL, DD, DD);

    // 3) GRU layer 0
    mma_gemm<4,0><<<dim3(3 * HID / 128, MALL / 128), 256, SMEM4>>>(p_t4, Wih0, bih0, p_xW, MALL, 3 * HID, DD);
    set_h<<<BATCH * HID / 256, 256>>>(h0);
    for (int t = 0; t < TSTEPS; t++) {
        mma_gemm<2,0><<<dim3(3 * HID / 128, BATCH / 64), 128, SMEM2>>>(p_h, Whh0, bhh0, p_hW, BATCH, 3 * HID, HID);
        gru_gate<<<BATCH * HID / 256, 256>>>(p_xW + (size_t)t * BATCH * 3 * HID, p_hW,
                                             p_h, p_hs + (size_t)t * BATCH * HID);
    }

    // 4) GRU layer 1
    mma_gemm<4,0><<<dim3(3 * HID / 128, MALL / 128), 256, SMEM4>>>(p_hs, Wih1, bih1, p_xW, MALL, 3 * HID, HID);
    set_h<<<BATCH * HID / 256, 256>>>(h0 + BATCH * HID);
    for (int t = 0; t < TSTEPS; t++) {
        mma_gemm<2,0><<<dim3(3 * HID / 128, BATCH / 64), 128, SMEM2>>>(p_h, Whh1, bhh1, p_hW, BATCH, 3 * HID, HID);
        gru_gate<<<BATCH * HID / 256, 256>>>(p_xW + (size_t)t * BATCH * 3 * HID, p_hW,
                                             p_h, nullptr);
    }

    // 5) final MLP -> out [1024]
    final_mlp<<<BATCH / 16, 256>>>(p_h, Wf0, bf0, Wf1, bf1, Wf2, bf2, out);
}

// round 17
// speedup vs baseline: 2.1643x; 1.1952x over previous
#include <cuda_runtime.h>
#include <cuda_bf16.h>
#include <math.h>

#define TSTEPS 12
#define BATCH  1024
#define HID    256
#define NN     4096
#define DD     256
#define MALL   (TSTEPS*BATCH)   // 12288
#define SW     20               // smem row stride in 32-bit words (conflict-free: gid*20+tig mod 32 distinct)

// ---------------- scratch (static device globals; no allocation) ----------------
__device__ float          g_coef[9*NN];
__device__ unsigned short g_xb[(size_t)MALL*NN];     // x in bf16 (96MB)
__device__ unsigned short g_Wpb[DD*NN];              // folded W' bf16
__device__ unsigned short g_t2b[MALL*DD];
__device__ unsigned short g_t4b[MALL*DD];
__device__ unsigned short g_Wlb[DD*DD];
__device__ unsigned short g_Wih0b[3*HID*DD];
__device__ unsigned short g_Whh0b[3*HID*HID];
__device__ unsigned short g_Wih1b[3*HID*HID];
__device__ unsigned short g_Whh1b[3*HID*HID];
__device__ float          g_xW[(size_t)MALL*3*HID];  // fp32 (36MB)
__device__ float          g_hW[BATCH*3*HID];
__device__ unsigned short g_hsb[MALL*HID];           // layer-0 outputs bf16
__device__ float          g_h [BATCH*HID];
__device__ unsigned short g_hb[BATCH*HID];

__device__ __forceinline__ float sigm(float x) { return 1.0f / (1.0f + expf(-x)); }

__device__ __forceinline__ unsigned short f2b(float f) {
    __nv_bfloat16 b = __float2bfloat16_rn(f);
    return *reinterpret_cast<unsigned short*>(&b);
}
__device__ __forceinline__ unsigned pack_bf2(float lo, float hi) {
    unsigned r;
    asm("cvt.rn.bf16x2.f32 %0, %1, %2;" : "=r"(r) : "f"(hi), "f"(lo));
    return r;
}

__device__ __forceinline__ void cpa16(void* smem_dst, const void* gmem_src) {
    unsigned s = (unsigned)__cvta_generic_to_shared(smem_dst);
    asm volatile("cp.async.cg.shared.global [%0], [%1], 16;\n" :: "r"(s), "l"(gmem_src));
}
#define CP_COMMIT() asm volatile("cp.async.commit_group;\n" ::: "memory")
#define CP_WAIT0()  asm volatile("cp.async.wait_group 0;\n" ::: "memory")
#define CP_WAIT1()  asm volatile("cp.async.wait_group 1;\n" ::: "memory")

__device__ __forceinline__ void mma_bf16(float* c, const unsigned* a, const unsigned* b) {
    asm volatile(
        "mma.sync.aligned.m16n8k16.row.col.f32.bf16.bf16.f32 "
        "{%0,%1,%2,%3}, {%4,%5,%6,%7}, {%8,%9}, {%0,%1,%2,%3};"
        : "+f"(c[0]), "+f"(c[1]), "+f"(c[2]), "+f"(c[3])
        : "r"(a[0]), "r"(a[1]), "r"(a[2]), "r"(a[3]), "r"(b[0]), "r"(b[1]));
}

// ---------------- fp32 -> bf16 conversion (vectorized by 4) ----------------
__global__ void f2bf_kernel(const float* __restrict__ in, unsigned short* __restrict__ out, int nq)
{
    int i = blockIdx.x * blockDim.x + threadIdx.x;
    if (i >= nq) return;
    float4 v = reinterpret_cast<const float4*>(in)[i];
    uint2 o;
    o.x = pack_bf2(v.x, v.y);
    o.y = pack_bf2(v.z, v.w);
    reinterpret_cast<uint2*>(out)[i] = o;
}

// ---------------- stage 0: fold sparse A into W_gnn ----------------
__global__ void extract_coef(const float* __restrict__ A)
{
    int n = blockIdx.x * blockDim.x + threadIdx.x;
    if (n >= NN) return;
    const int offs[9] = {0,-1,1,64,-64,63,65,-65,-63};
#pragma unroll
    for (int j = 0; j < 9; j++) {
        int m = n + offs[j];
        g_coef[j*NN + n] = (m >= 0 && m < NN) ? A[(size_t)m * NN + n] : 0.0f;
    }
}

__global__ void build_wp(const float* __restrict__ Wg)
{
    int n = blockIdx.x * blockDim.x + threadIdx.x;
    int d = blockIdx.y;
    if (n >= NN) return;
    const int offs[9] = {0,-1,1,64,-64,63,65,-65,-63};
    float s = 0.0f;
#pragma unroll
    for (int j = 0; j < 9; j++) {
        int m = n + offs[j];
        if (m >= 0 && m < NN)
            s = fmaf(g_coef[j*NN + n], Wg[(size_t)d * NN + m], s);
    }
    g_Wpb[(size_t)d * NN + n] = f2b(s);
}

// ---------------- bf16 tensor-core GEMM: C = act(A[M,K] @ W[N,K]^T + bias) ----------------
// m16n8k16 bf16, 3-stage cp.async, one __syncthreads per K-iter.
// Block tile (NWM*32) x 128, BK = 32 halves. Warp tile 32x64.
// Smem rows: 16 words of payload, stride SW=20 -> all fragment LDS conflict-free.
template<int NWM, int ACT, int OUTBF>
__global__ __launch_bounds__(NWM*64, 2)
void mma_gemm(const unsigned short* __restrict__ A,
              const unsigned short* __restrict__ W,
              const float* __restrict__ bias,
              void* __restrict__ Cout,
              int M, int N, int K)
{
    constexpr int THREADS = NWM * 64;
    constexpr int BM = NWM * 32;
    constexpr int AL = (BM * 4) / THREADS;       // A-staging quads per thread
    constexpr int WL = 512 / THREADS;            // W-staging quads per thread
    constexpr int STW = (BM + 128) * SW;         // words per stage

    extern __shared__ unsigned dsm[];

    const int tid  = threadIdx.x;
    const int wid  = tid >> 5;
    const int lane = tid & 31;
    const int gid  = lane >> 2;
    const int tig  = lane & 3;
    const int warp_m = wid % NWM;
    const int warp_n = wid / NWM;
    const int mBase = blockIdx.y * BM;
    const int nBase = blockIdx.x * 128;

    float acc[2][8][4];
#pragma unroll
    for (int mi = 0; mi < 2; mi++)
#pragma unroll
        for (int ni = 0; ni < 8; ni++)
#pragma unroll
            for (int j = 0; j < 4; j++) acc[mi][ni][j] = 0.0f;

    auto stage = [&](int s, int k0) {   // k0 in halves
        unsigned* As = dsm + s * STW;
        unsigned* Ws = As + BM * SW;
#pragma unroll
        for (int i = 0; i < AL; i++) {
            int idx = tid + i * THREADS;
            int r = idx >> 2, qc = idx & 3;
            cpa16(&As[r*SW + qc*4], A + (size_t)(mBase + r) * K + k0 + qc*8);
        }
#pragma unroll
        for (int i = 0; i < WL; i++) {
            int idx = tid + i * THREADS;
            int r = idx >> 2, qc = idx & 3;
            cpa16(&Ws[r*SW + qc*4], W + (size_t)(nBase + r) * K + k0 + qc*8);
        }
        CP_COMMIT();
    };

    const int nIter = K >> 5;                   // 32 halves per iter
    stage(0, 0);
    if (nIter > 1) stage(1, 32);

    for (int it = 0; it < nIter; it++) {
        if (it + 1 < nIter) { CP_WAIT1(); } else { CP_WAIT0(); }
        __syncthreads();
        if (it + 2 < nIter) stage((it + 2) % 3, (it + 2) << 5);

        const unsigned* As = dsm + (it % 3) * STW;
        const unsigned* Ws = As + BM * SW;
#pragma unroll
        for (int ks = 0; ks < 2; ks++) {        // two k16 steps
            const int kk = ks * 8;              // word offset
            unsigned af[2][4], bf[8][2];
#pragma unroll
            for (int mi = 0; mi < 2; mi++) {
                int mr = warp_m * 32 + mi * 16 + gid;
                af[mi][0] = As[(mr    )*SW + kk + tig];
                af[mi][1] = As[(mr + 8)*SW + kk + tig];
                af[mi][2] = As[(mr    )*SW + kk + tig + 4];
                af[mi][3] = As[(mr + 8)*SW + kk + tig + 4];
            }
#pragma unroll
            for (int ni = 0; ni < 8; ni++) {
                int nc = warp_n * 64 + ni * 8 + gid;
                bf[ni][0] = Ws[nc*SW + kk + tig];
                bf[ni][1] = Ws[nc*SW + kk + tig + 4];
            }
#pragma unroll
            for (int mi = 0; mi < 2; mi++)
#pragma unroll
                for (int ni = 0; ni < 8; ni++)
                    mma_bf16(acc[mi][ni], af[mi], bf[ni]);
        }
    }

#pragma unroll
    for (int mi = 0; mi < 2; mi++) {
        int m0 = mBase + warp_m * 32 + mi * 16 + gid;
#pragma unroll
        for (int ni = 0; ni < 8; ni++) {
            int n0 = nBase + warp_n * 64 + ni * 8 + tig * 2;
            float b0 = bias[n0], b1 = bias[n0 + 1];
            float v0 = acc[mi][ni][0] + b0;
            float v1 = acc[mi][ni][1] + b1;
            float v2 = acc[mi][ni][2] + b0;
            float v3 = acc[mi][ni][3] + b1;
            if (ACT) { v0 = sigm(v0); v1 = sigm(v1); v2 = sigm(v2); v3 = sigm(v3); }
            if (OUTBF) {
                unsigned short* C = (unsigned short*)Cout;
                *reinterpret_cast<unsigned*>(C + (size_t)m0 * N + n0)       = pack_bf2(v0, v1);
                *reinterpret_cast<unsigned*>(C + (size_t)(m0 + 8) * N + n0) = pack_bf2(v2, v3);
            } else {
                float* C = (float*)Cout;
                float2 lo; lo.x = v0; lo.y = v1;
                float2 hi; hi.x = v2; hi.y = v3;
                *reinterpret_cast<float2*>(C + (size_t)m0 * N + n0)       = lo;
                *reinterpret_cast<float2*>(C + (size_t)(m0 + 8) * N + n0) = hi;
            }
        }
    }
}

// ---------------- GRU pieces ----------------
__global__ void set_h(const float* __restrict__ src)
{
    int i = blockIdx.x * blockDim.x + threadIdx.x;
    float v = src[i];
    g_h[i] = v;
    g_hb[i] = f2b(v);
}

__global__ void gru_gate(const float* __restrict__ xW,
                         const float* __restrict__ hW,
                         unsigned short* __restrict__ hs_out)   // bf16 or null
{
    int idx = blockIdx.x * blockDim.x + threadIdx.x;
    int b = idx / HID, j = idx % HID;
    size_t base = (size_t)b * 3 * HID;
    float r = sigm(xW[base + j]          + hW[base + j]);
    float z = sigm(xW[base + HID + j]    + hW[base + HID + j]);
    float n = tanhf(xW[base + 2*HID + j] + r * hW[base + 2*HID + j]);
    float hp = g_h[idx];
    float hn = (1.0f - z) * n + z * hp;
    g_h[idx] = hn;
    unsigned short hb = f2b(hn);
    g_hb[idx] = hb;
    if (hs_out) hs_out[idx] = hb;
}

// ---------------- final 3-layer sigmoid MLP (fp32) ----------------
__global__ void final_mlp(const float* __restrict__ h,
                          const float* __restrict__ Wf0, const float* __restrict__ bf0,
                          const float* __restrict__ Wf1, const float* __restrict__ bf1,
                          const float* __restrict__ Wf2, const float* __restrict__ bf2,
                          float* __restrict__ out)
{
    __shared__ float sW0[16][257];
    __shared__ float sh [16][256];
    __shared__ float s1 [16][17];
    __shared__ float s2 [16][17];

    int tid = threadIdx.x;
    int bb  = blockIdx.x * 16;

    for (int i = tid; i < 16 * 256; i += 256) sW0[i / 256][i % 256] = Wf0[i];
    for (int i = tid; i < 16 * 256; i += 256) sh [i / 256][i % 256] = h[(size_t)bb * 256 + i];
    __syncthreads();

    int r = tid / 16, j = tid % 16;
    float a0 = bf0[j];
#pragma unroll 8
    for (int k = 0; k < 256; k++) a0 = fmaf(sh[r][k], sW0[j][k], a0);
    s1[r][j] = sigm(a0);
    __syncthreads();

    float a1 = bf1[j];
#pragma unroll
    for (int k = 0; k < 16; k++) a1 = fmaf(s1[r][k], Wf1[j * 16 + k], a1);
    s2[r][j] = sigm(a1);
    __syncthreads();

    if (j == 0) {
        float a2 = bf2[0];
#pragma unroll
        for (int k = 0; k < 16; k++) a2 = fmaf(s2[r][k], Wf2[k], a2);
        out[bb + r] = sigm(a2);
    }
}

// ---------------- launch ----------------
extern "C" void kernel_launch(void* const* d_in, const int* in_sizes, int n_in,
                              void* d_out, int out_size)
{
    const float* x     = (const float*)d_in[0];
    const float* h0    = (const float*)d_in[1];
    const float* Aadj  = (const float*)d_in[2];
    const float* W_gnn = (const float*)d_in[3];
    const float* b_gnn = (const float*)d_in[4];
    const float* W_lin = (const float*)d_in[5];
    const float* b_lin = (const float*)d_in[6];
    const float* Wih0  = (const float*)d_in[7];
    const float* Whh0  = (const float*)d_in[8];
    const float* bih0  = (const float*)d_in[9];
    const float* bhh0  = (const float*)d_in[10];
    const float* Wih1  = (const float*)d_in[11];
    const float* Whh1  = (const float*)d_in[12];
    const float* bih1  = (const float*)d_in[13];
    const float* bhh1  = (const float*)d_in[14];
    const float* Wf0   = (const float*)d_in[15];
    const float* bf0   = (const float*)d_in[16];
    const float* Wf1   = (const float*)d_in[17];
    const float* bf1   = (const float*)d_in[18];
    const float* Wf2   = (const float*)d_in[19];
    const float* bf2   = (const float*)d_in[20];
    float* out = (float*)d_out;

    unsigned short *p_xb, *p_Wpb, *p_t2b, *p_t4b, *p_Wlb;
    unsigned short *p_Wih0b, *p_Whh0b, *p_Wih1b, *p_Whh1b, *p_hsb, *p_hb;
    float *p_xW, *p_hW, *p_h;
    cudaGetSymbolAddress((void**)&p_xb,    g_xb);
    cudaGetSymbolAddress((void**)&p_Wpb,   g_Wpb);
    cudaGetSymbolAddress((void**)&p_t2b,   g_t2b);
    cudaGetSymbolAddress((void**)&p_t4b,   g_t4b);
    cudaGetSymbolAddress((void**)&p_Wlb,   g_Wlb);
    cudaGetSymbolAddress((void**)&p_Wih0b, g_Wih0b);
    cudaGetSymbolAddress((void**)&p_Whh0b, g_Whh0b);
    cudaGetSymbolAddress((void**)&p_Wih1b, g_Wih1b);
    cudaGetSymbolAddress((void**)&p_Whh1b, g_Whh1b);
    cudaGetSymbolAddress((void**)&p_hsb,   g_hsb);
    cudaGetSymbolAddress((void**)&p_hb,    g_hb);
    cudaGetSymbolAddress((void**)&p_xW,    g_xW);
    cudaGetSymbolAddress((void**)&p_hW,    g_hW);
    cudaGetSymbolAddress((void**)&p_h,     g_h);

    const int SMEM4 = 3 * (128 + 128) * SW * 4;   // 61440 B
    const int SMEM2 = 3 * ( 64 + 128) * SW * 4;   // 46080 B
    cudaFuncSetAttribute(mma_gemm<4,1,1>, cudaFuncAttributeMaxDynamicSharedMemorySize, SMEM4);
    cudaFuncSetAttribute(mma_gemm<4,0,0>, cudaFuncAttributeMaxDynamicSharedMemorySize, SMEM4);
    cudaFuncSetAttribute(mma_gemm<2,0,0>, cudaFuncAttributeMaxDynamicSharedMemorySize, SMEM2);

    // conversions
    f2bf_kernel<<<(MALL*NN/4 + 255)/256, 256>>>(x, p_xb, MALL*NN/4);
    f2bf_kernel<<<(DD*DD/4 + 255)/256, 256>>>(W_lin, p_Wlb, DD*DD/4);
    f2bf_kernel<<<(3*HID*DD/4 + 255)/256, 256>>>(Wih0, p_Wih0b, 3*HID*DD/4);
    f2bf_kernel<<<(3*HID*HID/4 + 255)/256, 256>>>(Whh0, p_Whh0b, 3*HID*HID/4);
    f2bf_kernel<<<(3*HID*HID/4 + 255)/256, 256>>>(Wih1, p_Wih1b, 3*HID*HID/4);
    f2bf_kernel<<<(3*HID*HID/4 + 255)/256, 256>>>(Whh1, p_Whh1b, 3*HID*HID/4);

    // 0) fold A into W_gnn (bf16 out)
    extract_coef<<<NN / 256, 256>>>(Aadj);
    build_wp<<<dim3(NN / 256, DD), 256>>>(W_gnn);

    // 1) t2 = sigmoid(x @ W'^T + b_gnn)   [12288,4096] x [4096,256]  bf16
    mma_gemm<4,1,1><<<dim3(DD / 128, MALL / 128), 256, SMEM4>>>(p_xb, p_Wpb, b_gnn, p_t2b, MALL, DD, NN);

    // 2) t4 = sigmoid(t2 @ W_lin^T + b_lin)
    mma_gemm<4,1,1><<<dim3(DD / 128, MALL / 128), 256, SMEM4>>>(p_t2b, p_Wlb, b_lin, p_t4b, MALL, DD, DD);

    // 3) GRU layer 0
    mma_gemm<4,0,0><<<dim3(3 * HID / 128, MALL / 128), 256, SMEM4>>>(p_t4b, p_Wih0b, bih0, p_xW, MALL, 3 * HID, DD);
    set_h<<<BATCH * HID / 256, 256>>>(h0);
    for (int t = 0; t < TSTEPS; t++) {
        mma_gemm<2,0,0><<<dim3(3 * HID / 128, BATCH / 64), 128, SMEM2>>>(p_hb, p_Whh0b, bhh0, p_hW, BATCH, 3 * HID, HID);
        gru_gate<<<BATCH * HID / 256, 256>>>(p_xW + (size_t)t * BATCH * 3 * HID, p_hW,
                                             p_hsb + (size_t)t * BATCH * HID);
    }

    // 4) GRU layer 1
    mma_gemm<4,0,0><<<dim3(3 * HID / 128, MALL / 128), 256, SMEM4>>>(p_hsb, p_Wih1b, bih1, p_xW, MALL, 3 * HID, HID);
    set_h<<<BATCH * HID / 256, 256>>>(h0 + BATCH * HID);
    for (int t = 0; t < TSTEPS; t++) {
        mma_gemm<2,0,0><<<dim3(3 * HID / 128, BATCH / 64), 128, SMEM2>>>(p_hb, p_Whh1b, bhh1, p_hW, BATCH, 3 * HID, HID);
        gru_gate<<<BATCH * HID / 256, 256>>>(p_xW + (size_t)t * BATCH * 3 * HID, p_hW, nullptr);
    }

    // 5) final MLP -> out [1024]
    final_mlp<<<BATCH / 16, 256>>>(p_h, Wf0, bf0, Wf1, bf1, Wf2, bf2, out);
}